// round 8
// baseline (speedup 1.0000x reference)
#include <cuda_runtime.h>
#include <cuda_bf16.h>
#include <math.h>

// LRML memory-network scoring — G=16 lanes/element, packed f32x2 math.
//  0: user_ids  int32  [B]
//  1: item_ids  int32  [B]
//  2: user_emb  f32    [U, 32]
//  3: item_emb  f32    [I, 32]
//  4: W_att     f32    [10, 32]
//  5: memory    f32    [10, 32]
// Output: f32 [B] = -sum((ue + rel - ie)^2)
//
// Lane `sub` (0..15) owns dims [2*sub, 2*sub+2) as ONE f32x2 per table.
// One warp covers 2 elements; 8192 warps total (~56/SM resident, 1 wave).

#define M 10
#define TPB 256               // 8 warps -> 16 elements per block

typedef unsigned long long u64t;

__device__ __forceinline__ u64t fma2(u64t a, u64t b, u64t c) {
    u64t d;
    asm("fma.rn.f32x2 %0, %1, %2, %3;" : "=l"(d) : "l"(a), "l"(b), "l"(c));
    return d;
}
__device__ __forceinline__ u64t mul2(u64t a, u64t b) {
    u64t d;
    asm("mul.rn.f32x2 %0, %1, %2;" : "=l"(d) : "l"(a), "l"(b));
    return d;
}
__device__ __forceinline__ u64t pack2(float lo, float hi) {
    u64t d;
    asm("mov.b64 %0, {%1, %2};" : "=l"(d) : "f"(lo), "f"(hi));
    return d;
}
__device__ __forceinline__ float hadd2(u64t a) {   // lo + hi
    float x, y;
    asm("mov.b64 {%0, %1}, %2;" : "=f"(x), "=f"(y) : "l"(a));
    return x + y;
}
__device__ __forceinline__ float ex2a(float x) {   // 2^x, MUFU
    float y;
    asm("ex2.approx.f32 %0, %1;" : "=f"(y) : "f"(x));
    return y;
}
__device__ __forceinline__ float rcpa(float x) {   // 1/x, MUFU
    float y;
    asm("rcp.approx.f32 %0, %1;" : "=f"(y) : "f"(x));
    return y;
}

__global__ __launch_bounds__(TPB, 7)
void LRML_90804198572513_kernel(const int* __restrict__ user_ids,
                                const int* __restrict__ item_ids,
                                const float* __restrict__ user_emb,
                                const float* __restrict__ item_emb,
                                const float* __restrict__ W_att,
                                const float* __restrict__ memory,
                                float* __restrict__ out,
                                int B) {
    __shared__ __align__(16) u64t sW[M * 16];   // W_att rows as 16 f32x2 each
    __shared__ __align__(16) u64t sM[M * 16];   // memory rows

    const int tid  = threadIdx.x;
    const int lane = tid & 31;
    const int warp = tid >> 5;
    const int sub  = lane & 15;       // dim-slice owner (0..15)
    const int eg   = lane >> 4;       // element within warp (0..1)
    const int b = ((blockIdx.x * (TPB / 32) + warp) << 1) + eg;
    const int bb = (b < B) ? b : (B - 1);

    // 1) ids (dependent DRAM/L2 load — issue first)
    const int uid = user_ids[bb];
    const int iid = item_ids[bb];

    // 2) stage parameter matrices (independent loads; overlap id latency)
    u64t wreg, mreg;
    const bool stager = (tid < M * 16);
    if (stager) {
        wreg = ((const u64t*)W_att)[tid];
        mreg = ((const u64t*)memory)[tid];
    }

    // 3) row gathers. 16 lanes x 8B cover a full 128B row (coalesced LDG.64).
    const u64t u  = ((const u64t*)(user_emb + (size_t)uid * 32))[sub];
    const u64t iv = ((const u64t*)(item_emb + (size_t)iid * 32))[sub];

    if (stager) { sW[tid] = wreg; sM[tid] = mreg; }
    __syncthreads();

    // 4) per-lane partials: norms + unscaled scores (one f32x2 per lane)
    float red[2 + M];
    red[0] = hadd2(mul2(u,  u));     // |u|^2 partial
    red[1] = hadd2(mul2(iv, iv));    // |i|^2 partial

    const u64t j = mul2(u, iv);      // unscaled joint slice
    #pragma unroll
    for (int m = 0; m < M; m++)
        red[2 + m] = hadd2(mul2(j, sW[m * 16 + sub]));

    // 5) merged 4-stage butterfly over the 16-lane group (12 values, pipelined)
    #pragma unroll
    for (int o = 1; o <= 8; o <<= 1) {
        #pragma unroll
        for (int k = 0; k < 2 + M; k++)
            red[k] += __shfl_xor_sync(0xFFFFFFFFu, red[k], o);
    }

    // 6) scales; fold renorm product and log2(e) into one exp multiplier.
    //    scale = 1/max(||e||,1) = min(rsqrt(n),1)   (n=0 -> inf -> 1, fine)
    const float su  = fminf(rsqrtf(red[0]), 1.0f);
    const float si  = fminf(rsqrtf(red[1]), 1.0f);
    const float sjE = su * si * 1.44269504f;

    // 7) softmax denominator (no max-subtract: |score| <~ 4, fp32-safe)
    float sum = 0.0f;
    #pragma unroll
    for (int m = 0; m < M; m++) sum += ex2a(red[2 + m] * sjE);
    const float inv = rcpa(sum);

    // 8) unnormalized rel for this lane's 2 dims (exp recomputed — keeps
    //    regs low; MUFU slots are free in this stall-dominated stream)
    u64t r = 0ull;
    #pragma unroll
    for (int m = 0; m < M; m++) {
        const float em = ex2a(red[2 + m] * sjE);
        r = fma2(pack2(em, em), sM[m * 16 + sub], r);
    }

    // 9) dist slice: dx = su*u + inv*r - si*i (packed), square, group-reduce
    const u64t dx = fma2(pack2(su, su), u,
                    fma2(pack2(-si, -si), iv,
                         mul2(pack2(inv, inv), r)));
    float d = hadd2(mul2(dx, dx));
    d += __shfl_xor_sync(0xFFFFFFFFu, d, 1);
    d += __shfl_xor_sync(0xFFFFFFFFu, d, 2);
    d += __shfl_xor_sync(0xFFFFFFFFu, d, 4);
    d += __shfl_xor_sync(0xFFFFFFFFu, d, 8);

    if (sub == 0 && b < B) out[b] = -d;
}

extern "C" void kernel_launch(void* const* d_in, const int* in_sizes, int n_in,
                              void* d_out, int out_size) {
    const int*   user_ids = (const int*)  d_in[0];
    const int*   item_ids = (const int*)  d_in[1];
    const float* user_emb = (const float*)d_in[2];
    const float* item_emb = (const float*)d_in[3];
    const float* W_att    = (const float*)d_in[4];
    const float* memory   = (const float*)d_in[5];
    float* out = (float*)d_out;

    const int B = in_sizes[0];
    const int elems_per_block = (TPB / 32) * 2;  // 16
    const int grid = (B + elems_per_block - 1) / elems_per_block;
    LRML_90804198572513_kernel<<<grid, TPB>>>(
        user_ids, item_ids, user_emb, item_emb, W_att, memory, out, B);
}

// round 9
// speedup vs baseline: 1.2804x; 1.2804x over previous
#include <cuda_runtime.h>
#include <cuda_bf16.h>
#include <math.h>

// LRML memory-network scoring — G=8 lanes/element, packed f32x2 math,
// hoisted LDS + split accumulator chains (R6 shape, trimmed stream).
//  0: user_ids  int32  [B]
//  1: item_ids  int32  [B]
//  2: user_emb  f32    [U, 32]
//  3: item_emb  f32    [I, 32]
//  4: W_att     f32    [10, 32]
//  5: memory    f32    [10, 32]
// Output: f32 [B] = -sum((ue + rel - ie)^2)
//
// Lane `sub` (0..7) owns dims [4*sub, 4*sub+4) as one ulonglong2
// (= two f32x2 packed pairs). One warp covers 4 elements; 4096 warps.

#define M 10
#define TPB 128               // 4 warps -> 16 elements per block

typedef unsigned long long u64t;

__device__ __forceinline__ u64t fma2(u64t a, u64t b, u64t c) {
    u64t d;
    asm("fma.rn.f32x2 %0, %1, %2, %3;" : "=l"(d) : "l"(a), "l"(b), "l"(c));
    return d;
}
__device__ __forceinline__ u64t mul2(u64t a, u64t b) {
    u64t d;
    asm("mul.rn.f32x2 %0, %1, %2;" : "=l"(d) : "l"(a), "l"(b));
    return d;
}
__device__ __forceinline__ u64t pack2(float lo, float hi) {
    u64t d;
    asm("mov.b64 %0, {%1, %2};" : "=l"(d) : "f"(lo), "f"(hi));
    return d;
}
__device__ __forceinline__ float hadd2(u64t a) {   // lo + hi
    float x, y;
    asm("mov.b64 {%0, %1}, %2;" : "=f"(x), "=f"(y) : "l"(a));
    return x + y;
}
__device__ __forceinline__ float ex2a(float x) {   // 2^x, MUFU
    float y;
    asm("ex2.approx.f32 %0, %1;" : "=f"(y) : "f"(x));
    return y;
}
__device__ __forceinline__ float rcpa(float x) {   // 1/x, MUFU
    float y;
    asm("rcp.approx.f32 %0, %1;" : "=f"(y) : "f"(x));
    return y;
}

__global__ __launch_bounds__(TPB, 7)
void LRML_90804198572513_kernel(const int* __restrict__ user_ids,
                                const int* __restrict__ item_ids,
                                const float* __restrict__ user_emb,
                                const float* __restrict__ item_emb,
                                const float* __restrict__ W_att,
                                const float* __restrict__ memory,
                                float* __restrict__ out,
                                int B) {
    __shared__ __align__(16) ulonglong2 sW[M * 8];  // W_att rows, 8 x 16B each
    __shared__ __align__(16) ulonglong2 sM[M * 8];  // memory rows

    const int tid  = threadIdx.x;
    const int lane = tid & 31;
    const int warp = tid >> 5;
    const int sub  = lane & 7;        // dim-slice owner (0..7)
    const int eg   = lane >> 3;       // element within warp (0..3)
    const int b = ((blockIdx.x * (TPB / 32) + warp) << 2) + eg;
    const int bb = (b < B) ? b : (B - 1);

    // 1) ids (dependent DRAM/L2 load — issue first)
    const int uid = user_ids[bb];
    const int iid = item_ids[bb];

    // 2) stage parameter matrices (independent loads; overlap id latency)
    ulonglong2 wreg, mreg;
    const bool stager = (tid < M * 8);
    if (stager) {
        wreg = ((const ulonglong2*)W_att)[tid];
        mreg = ((const ulonglong2*)memory)[tid];
    }

    // 3) row gathers (dependent on ids). Lanes 0..7 cover a full 128B row.
    const ulonglong2 u  = ((const ulonglong2*)(user_emb + (size_t)uid * 32))[sub];
    const ulonglong2 iv = ((const ulonglong2*)(item_emb + (size_t)iid * 32))[sub];

    if (stager) { sW[tid] = wreg; sM[tid] = mreg; }
    __syncthreads();

    // 4) per-lane partials: norms + unscaled scores (packed math)
    float red[2 + M];
    red[0] = hadd2(fma2(u.y,  u.y,  mul2(u.x,  u.x)));
    red[1] = hadd2(fma2(iv.y, iv.y, mul2(iv.x, iv.x)));

    const u64t j0 = mul2(u.x, iv.x);   // unscaled joint slice
    const u64t j1 = mul2(u.y, iv.y);
    #pragma unroll
    for (int m = 0; m < M; m++) {
        const ulonglong2 w = sW[m * 8 + sub];
        red[2 + m] = hadd2(fma2(j1, w.y, mul2(j0, w.x)));
    }

    // Hoist half the memory-row LDS loads: independent of red[], they fill
    // the butterfly's stall slots and shorten the post-softmax chain.
    ulonglong2 mm0 = sM[0 * 8 + sub];
    ulonglong2 mm1 = sM[1 * 8 + sub];
    ulonglong2 mm2 = sM[2 * 8 + sub];
    ulonglong2 mm3 = sM[3 * 8 + sub];
    ulonglong2 mm4 = sM[4 * 8 + sub];

    // 5) merged 3-stage butterfly over the 8-lane group (12 values, pipelined)
    #pragma unroll
    for (int o = 1; o <= 4; o <<= 1) {
        #pragma unroll
        for (int k = 0; k < 2 + M; k++)
            red[k] += __shfl_xor_sync(0xFFFFFFFFu, red[k], o);
    }

    // 6) scales; fold renorm product and log2(e) into one exp multiplier.
    //    scale = 1/max(||e||,1) = min(rsqrt(n),1)   (n=0 -> inf -> 1, fine)
    const float su  = fminf(rsqrtf(red[0]), 1.0f);
    const float si  = fminf(rsqrtf(red[1]), 1.0f);
    const float sjE = su * si * 1.44269504f;

    // 7) softmax numerators (no max-subtract: |score| <~ 4, fp32-safe);
    //    two partial sums to halve the FADD chain.
    float e[M];
    #pragma unroll
    for (int m = 0; m < M; m++) e[m] = ex2a(red[2 + m] * sjE);
    float sumA = e[0] + e[2], sumB = e[1] + e[3];
    sumA += e[4] + e[6]; sumB += e[5] + e[7];
    sumA += e[8];        sumB += e[9];
    const float inv = rcpa(sumA + sumB);

    // 8) unnormalized rel, two independent accumulator chains.
    u64t ra = mul2(pack2(e[0], e[0]), mm0.x);
    u64t rb = mul2(pack2(e[0], e[0]), mm0.y);
    u64t rc = mul2(pack2(e[1], e[1]), mm1.x);
    u64t rd = mul2(pack2(e[1], e[1]), mm1.y);
    ra = fma2(pack2(e[2], e[2]), mm2.x, ra);
    rb = fma2(pack2(e[2], e[2]), mm2.y, rb);
    rc = fma2(pack2(e[3], e[3]), mm3.x, rc);
    rd = fma2(pack2(e[3], e[3]), mm3.y, rd);
    ra = fma2(pack2(e[4], e[4]), mm4.x, ra);
    rb = fma2(pack2(e[4], e[4]), mm4.y, rb);
    #pragma unroll
    for (int m = 5; m < M; m += 2) {
        const ulonglong2 ma = sM[m * 8 + sub];
        rc = fma2(pack2(e[m], e[m]), ma.x, rc);
        rd = fma2(pack2(e[m], e[m]), ma.y, rd);
        if (m + 1 < M) {
            const ulonglong2 mb = sM[(m + 1) * 8 + sub];
            ra = fma2(pack2(e[m + 1], e[m + 1]), mb.x, ra);
            rb = fma2(pack2(e[m + 1], e[m + 1]), mb.y, rb);
        }
    }
    const u64t r0 = fma2(pack2(1.f, 1.f), rc, ra);  // ra+rc
    const u64t r1 = fma2(pack2(1.f, 1.f), rd, rb);  // rb+rd

    // 9) dist: dx = su*u + inv*r - si*i (packed), square, group-reduce
    const u64t su2  = pack2(su, su);
    const u64t nsi2 = pack2(-si, -si);
    const u64t inv2 = pack2(inv, inv);
    const u64t dx0 = fma2(su2, u.x, fma2(nsi2, iv.x, mul2(inv2, r0)));
    const u64t dx1 = fma2(su2, u.y, fma2(nsi2, iv.y, mul2(inv2, r1)));
    float d = hadd2(fma2(dx1, dx1, mul2(dx0, dx0)));
    d += __shfl_xor_sync(0xFFFFFFFFu, d, 1);
    d += __shfl_xor_sync(0xFFFFFFFFu, d, 2);
    d += __shfl_xor_sync(0xFFFFFFFFu, d, 4);

    if (sub == 0 && b < B) out[b] = -d;
}

extern "C" void kernel_launch(void* const* d_in, const int* in_sizes, int n_in,
                              void* d_out, int out_size) {
    const int*   user_ids = (const int*)  d_in[0];
    const int*   item_ids = (const int*)  d_in[1];
    const float* user_emb = (const float*)d_in[2];
    const float* item_emb = (const float*)d_in[3];
    const float* W_att    = (const float*)d_in[4];
    const float* memory   = (const float*)d_in[5];
    float* out = (float*)d_out;

    const int B = in_sizes[0];
    const int elems_per_block = (TPB / 32) * 4;  // 16
    const int grid = (B + elems_per_block - 1) / elems_per_block;
    LRML_90804198572513_kernel<<<grid, TPB>>>(
        user_ids, item_ids, user_emb, item_emb, W_att, memory, out, B);
}

// round 10
// speedup vs baseline: 1.3094x; 1.0226x over previous
#include <cuda_runtime.h>
#include <cuda_bf16.h>
#include <math.h>

// LRML memory-network scoring — G=8 lanes/element, packed f32x2,
// BARRIER-FREE: no shared memory, params read via L1-resident LDG.
//  0: user_ids  int32  [B]
//  1: item_ids  int32  [B]
//  2: user_emb  f32    [U, 32]
//  3: item_emb  f32    [I, 32]
//  4: W_att     f32    [10, 32]
//  5: memory    f32    [10, 32]
// Output: f32 [B] = -sum((ue + rel - ie)^2)
//
// Lane `sub` (0..7) owns dims [4*sub, 4*sub+4) as one ulonglong2
// (two f32x2 pairs). One warp covers 4 elements; 4096 warps total.
// No __syncthreads anywhere: warps never convoy on each other.

#define M 10
#define TPB 128               // 4 warps -> 16 elements per block

typedef unsigned long long u64t;

__device__ __forceinline__ u64t fma2(u64t a, u64t b, u64t c) {
    u64t d;
    asm("fma.rn.f32x2 %0, %1, %2, %3;" : "=l"(d) : "l"(a), "l"(b), "l"(c));
    return d;
}
__device__ __forceinline__ u64t mul2(u64t a, u64t b) {
    u64t d;
    asm("mul.rn.f32x2 %0, %1, %2;" : "=l"(d) : "l"(a), "l"(b));
    return d;
}
__device__ __forceinline__ u64t pack2(float lo, float hi) {
    u64t d;
    asm("mov.b64 %0, {%1, %2};" : "=l"(d) : "f"(lo), "f"(hi));
    return d;
}
__device__ __forceinline__ float hadd2(u64t a) {   // lo + hi
    float x, y;
    asm("mov.b64 {%0, %1}, %2;" : "=f"(x), "=f"(y) : "l"(a));
    return x + y;
}
__device__ __forceinline__ float ex2a(float x) {   // 2^x, MUFU
    float y;
    asm("ex2.approx.f32 %0, %1;" : "=f"(y) : "f"(x));
    return y;
}
__device__ __forceinline__ float rcpa(float x) {   // 1/x, MUFU
    float y;
    asm("rcp.approx.f32 %0, %1;" : "=f"(y) : "f"(x));
    return y;
}

__global__ __launch_bounds__(TPB, 7)
void LRML_90804198572513_kernel(const int* __restrict__ user_ids,
                                const int* __restrict__ item_ids,
                                const float* __restrict__ user_emb,
                                const float* __restrict__ item_emb,
                                const float* __restrict__ W_att,
                                const float* __restrict__ memory,
                                float* __restrict__ out,
                                int B) {
    const int tid  = threadIdx.x;
    const int lane = tid & 31;
    const int warp = tid >> 5;
    const int sub  = lane & 7;        // dim-slice owner (0..7)
    const int eg   = lane >> 3;       // element within warp (0..3)
    const int b = ((blockIdx.x * (TPB / 32) + warp) << 2) + eg;
    const int bb = (b < B) ? b : (B - 1);

    // 1) ids first (dependent DRAM/L2 load)
    const int uid = __ldg(&user_ids[bb]);
    const int iid = __ldg(&item_ids[bb]);

    // 2) row gathers. Lanes 0..7 of a group cover one full 128B row.
    const ulonglong2 u  = __ldg((const ulonglong2*)(user_emb + (size_t)uid * 32) + sub);
    const ulonglong2 iv = __ldg((const ulonglong2*)(item_emb + (size_t)iid * 32) + sub);

    // Parameter rows: broadcast-coalesced LDG, L1-resident after first touch.
    const ulonglong2* Wp = (const ulonglong2*)W_att  + sub;
    const ulonglong2* Mp = (const ulonglong2*)memory + sub;

    // 3) per-lane partials: norms + unscaled scores (packed math)
    float red[2 + M];
    red[0] = hadd2(fma2(u.y,  u.y,  mul2(u.x,  u.x)));
    red[1] = hadd2(fma2(iv.y, iv.y, mul2(iv.x, iv.x)));

    const u64t j0 = mul2(u.x, iv.x);   // unscaled joint slice
    const u64t j1 = mul2(u.y, iv.y);
    #pragma unroll
    for (int m = 0; m < M; m++) {
        const ulonglong2 w = __ldg(Wp + m * 8);
        red[2 + m] = hadd2(fma2(j1, w.y, mul2(j0, w.x)));
    }

    // 4) merged 3-stage butterfly over the 8-lane group (12 values, pipelined)
    #pragma unroll
    for (int o = 1; o <= 4; o <<= 1) {
        #pragma unroll
        for (int k = 0; k < 2 + M; k++)
            red[k] += __shfl_xor_sync(0xFFFFFFFFu, red[k], o);
    }

    // 5) scales; fold renorm product and log2(e) into one exp multiplier.
    //    scale = 1/max(||e||,1) = min(rsqrt(n),1)   (n=0 -> inf -> 1, fine)
    const float su  = fminf(rsqrtf(red[0]), 1.0f);
    const float si  = fminf(rsqrtf(red[1]), 1.0f);
    const float sjE = su * si * 1.44269504f;

    // 6) softmax numerators (no max-subtract: |score| <~ 4, fp32-safe);
    //    two partial sums to halve the FADD chain.
    float e[M];
    #pragma unroll
    for (int m = 0; m < M; m++) e[m] = ex2a(red[2 + m] * sjE);
    float sumA = e[0] + e[2], sumB = e[1] + e[3];
    sumA += e[4] + e[6]; sumB += e[5] + e[7];
    sumA += e[8];        sumB += e[9];
    const float inv = rcpa(sumA + sumB);

    // 7) unnormalized rel for this lane's 4 dims; 2 independent chains.
    u64t ra0 = 0ull, ra1 = 0ull, rb0 = 0ull, rb1 = 0ull;
    #pragma unroll
    for (int m = 0; m < M; m += 2) {
        const ulonglong2 ma = __ldg(Mp + m * 8);
        const ulonglong2 mb = __ldg(Mp + (m + 1) * 8);
        const u64t pa = pack2(e[m], e[m]);
        const u64t pb = pack2(e[m + 1], e[m + 1]);
        ra0 = fma2(pa, ma.x, ra0);
        ra1 = fma2(pa, ma.y, ra1);
        rb0 = fma2(pb, mb.x, rb0);
        rb1 = fma2(pb, mb.y, rb1);
    }
    const u64t one2 = pack2(1.0f, 1.0f);
    const u64t r0 = fma2(one2, rb0, ra0);
    const u64t r1 = fma2(one2, rb1, ra1);

    // 8) dist: dx = su*u + inv*r - si*i (packed), square, group-reduce
    const u64t su2  = pack2(su, su);
    const u64t nsi2 = pack2(-si, -si);
    const u64t inv2 = pack2(inv, inv);
    const u64t dx0 = fma2(su2, u.x, fma2(nsi2, iv.x, mul2(inv2, r0)));
    const u64t dx1 = fma2(su2, u.y, fma2(nsi2, iv.y, mul2(inv2, r1)));
    float d = hadd2(fma2(dx1, dx1, mul2(dx0, dx0)));
    d += __shfl_xor_sync(0xFFFFFFFFu, d, 1);
    d += __shfl_xor_sync(0xFFFFFFFFu, d, 2);
    d += __shfl_xor_sync(0xFFFFFFFFu, d, 4);

    if (sub == 0 && b < B) out[b] = -d;
}

extern "C" void kernel_launch(void* const* d_in, const int* in_sizes, int n_in,
                              void* d_out, int out_size) {
    const int*   user_ids = (const int*)  d_in[0];
    const int*   item_ids = (const int*)  d_in[1];
    const float* user_emb = (const float*)d_in[2];
    const float* item_emb = (const float*)d_in[3];
    const float* W_att    = (const float*)d_in[4];
    const float* memory   = (const float*)d_in[5];
    float* out = (float*)d_out;

    const int B = in_sizes[0];
    const int elems_per_block = (TPB / 32) * 4;  // 16
    const int grid = (B + elems_per_block - 1) / elems_per_block;
    LRML_90804198572513_kernel<<<grid, TPB>>>(
        user_ids, item_ids, user_emb, item_emb, W_att, memory, out, B);
}

// round 13
// speedup vs baseline: 1.6763x; 1.2802x over previous
#include <cuda_runtime.h>
#include <cuda_bf16.h>
#include <math.h>

// LRML memory-network scoring — G=4 lanes/element, packed f32x2,
// barrier-free, 2-stage merged butterflies (SHFL amortized over 8 elem/warp).
// (R11 rev: fixed parameter-row stride — 8 ulonglong2 per 32-float row.)
//  0: user_ids  int32  [B]
//  1: item_ids  int32  [B]
//  2: user_emb  f32    [U, 32]
//  3: item_emb  f32    [I, 32]
//  4: W_att     f32    [10, 32]
//  5: memory    f32    [10, 32]
// Output: f32 [B] = -sum((ue + rel - ie)^2)
//
// Lane `sub` (0..3) owns dims [8*sub, 8*sub+8) as two ulonglong2
// (= four f32x2 pairs). One warp covers 8 elements; 2048 warps total.

#define M 10
#define TPB 128               // 4 warps -> 32 elements per block

typedef unsigned long long u64t;

__device__ __forceinline__ u64t fma2(u64t a, u64t b, u64t c) {
    u64t d;
    asm("fma.rn.f32x2 %0, %1, %2, %3;" : "=l"(d) : "l"(a), "l"(b), "l"(c));
    return d;
}
__device__ __forceinline__ u64t mul2(u64t a, u64t b) {
    u64t d;
    asm("mul.rn.f32x2 %0, %1, %2;" : "=l"(d) : "l"(a), "l"(b));
    return d;
}
__device__ __forceinline__ u64t pack2(float lo, float hi) {
    u64t d;
    asm("mov.b64 %0, {%1, %2};" : "=l"(d) : "f"(lo), "f"(hi));
    return d;
}
__device__ __forceinline__ float hadd2(u64t a) {   // lo + hi
    float x, y;
    asm("mov.b64 {%0, %1}, %2;" : "=f"(x), "=f"(y) : "l"(a));
    return x + y;
}
__device__ __forceinline__ float ex2a(float x) {   // 2^x, MUFU
    float y;
    asm("ex2.approx.f32 %0, %1;" : "=f"(y) : "f"(x));
    return y;
}
__device__ __forceinline__ float rcpa(float x) {   // 1/x, MUFU
    float y;
    asm("rcp.approx.f32 %0, %1;" : "=f"(y) : "f"(x));
    return y;
}

__global__ __launch_bounds__(TPB, 7)
void LRML_90804198572513_kernel(const int* __restrict__ user_ids,
                                const int* __restrict__ item_ids,
                                const float* __restrict__ user_emb,
                                const float* __restrict__ item_emb,
                                const float* __restrict__ W_att,
                                const float* __restrict__ memory,
                                float* __restrict__ out,
                                int B) {
    const int tid  = threadIdx.x;
    const int lane = tid & 31;
    const int warp = tid >> 5;
    const int sub  = lane & 3;        // 8-dim slice owner (0..3)
    const int eg   = lane >> 2;       // element within warp (0..7)
    const int b = ((blockIdx.x * (TPB / 32) + warp) << 3) + eg;
    const int bb = (b < B) ? b : (B - 1);

    // 1) ids first (dependent DRAM/L2 load)
    const int uid = __ldg(&user_ids[bb]);
    const int iid = __ldg(&item_ids[bb]);

    // 2) row gathers: lanes 0..3 of a group cover one full 128B row
    //    (two 16B loads per lane -> 2 coalesced LDG.128 per table).
    const ulonglong2* ubase = (const ulonglong2*)(user_emb + (size_t)uid * 32) + sub * 2;
    const ulonglong2* ibase = (const ulonglong2*)(item_emb + (size_t)iid * 32) + sub * 2;
    const ulonglong2 u0 = __ldg(ubase);
    const ulonglong2 u1 = __ldg(ubase + 1);
    const ulonglong2 i0 = __ldg(ibase);
    const ulonglong2 i1 = __ldg(ibase + 1);

    // Parameter slices: broadcast-coalesced LDG, L1-resident after 1st touch.
    // Row stride = 32 floats = 8 ulonglong2. Lane takes entries sub*2, sub*2+1.
    const ulonglong2* Wp = (const ulonglong2*)W_att  + sub * 2;
    const ulonglong2* Mp = (const ulonglong2*)memory + sub * 2;

    // 3) per-lane partials: norms + unscaled scores (packed math)
    float red[2 + M];
    red[0] = hadd2(fma2(u1.y, u1.y, fma2(u1.x, u1.x,
                   fma2(u0.y, u0.y, mul2(u0.x, u0.x)))));
    red[1] = hadd2(fma2(i1.y, i1.y, fma2(i1.x, i1.x,
                   fma2(i0.y, i0.y, mul2(i0.x, i0.x)))));

    const u64t j0 = mul2(u0.x, i0.x);   // unscaled joint slice (4 f32x2)
    const u64t j1 = mul2(u0.y, i0.y);
    const u64t j2 = mul2(u1.x, i1.x);
    const u64t j3 = mul2(u1.y, i1.y);
    #pragma unroll
    for (int m = 0; m < M; m++) {
        const ulonglong2 w0 = __ldg(Wp + m * 8);       // row stride 8!
        const ulonglong2 w1 = __ldg(Wp + m * 8 + 1);
        red[2 + m] = hadd2(fma2(j3, w1.y, fma2(j2, w1.x,
                           fma2(j1, w0.y, mul2(j0, w0.x)))));
    }

    // 4) merged 2-stage butterfly over the 4-lane group (12 values, pipelined)
    #pragma unroll
    for (int o = 1; o <= 2; o <<= 1) {
        #pragma unroll
        for (int k = 0; k < 2 + M; k++)
            red[k] += __shfl_xor_sync(0xFFFFFFFFu, red[k], o);
    }

    // 5) scales; fold renorm product and log2(e) into one exp multiplier.
    //    scale = 1/max(||e||,1) = min(rsqrt(n),1)   (n=0 -> inf -> 1, fine)
    const float su  = fminf(rsqrtf(red[0]), 1.0f);
    const float si  = fminf(rsqrtf(red[1]), 1.0f);
    const float sjE = su * si * 1.44269504f;

    // 6) softmax numerators (no max-subtract: |score| <~ 4, fp32-safe)
    float e[M];
    #pragma unroll
    for (int m = 0; m < M; m++) e[m] = ex2a(red[2 + m] * sjE);
    float sumA = e[0] + e[2], sumB = e[1] + e[3];
    sumA += e[4] + e[6]; sumB += e[5] + e[7];
    sumA += e[8];        sumB += e[9];
    const float inv = rcpa(sumA + sumB);

    // 7) unnormalized rel over this lane's 8 dims; even/odd m chains.
    u64t a0 = 0ull, a1 = 0ull, a2 = 0ull, a3 = 0ull;   // even m
    u64t c0 = 0ull, c1 = 0ull, c2 = 0ull, c3 = 0ull;   // odd  m
    #pragma unroll
    for (int m = 0; m < M; m += 2) {
        const ulonglong2 ma0 = __ldg(Mp + m * 8);          // row stride 8!
        const ulonglong2 ma1 = __ldg(Mp + m * 8 + 1);
        const ulonglong2 mb0 = __ldg(Mp + (m + 1) * 8);
        const ulonglong2 mb1 = __ldg(Mp + (m + 1) * 8 + 1);
        const u64t pa = pack2(e[m], e[m]);
        const u64t pb = pack2(e[m + 1], e[m + 1]);
        a0 = fma2(pa, ma0.x, a0);  a1 = fma2(pa, ma0.y, a1);
        a2 = fma2(pa, ma1.x, a2);  a3 = fma2(pa, ma1.y, a3);
        c0 = fma2(pb, mb0.x, c0);  c1 = fma2(pb, mb0.y, c1);
        c2 = fma2(pb, mb1.x, c2);  c3 = fma2(pb, mb1.y, c3);
    }
    const u64t one2 = pack2(1.0f, 1.0f);
    const u64t r0 = fma2(one2, c0, a0);
    const u64t r1 = fma2(one2, c1, a1);
    const u64t r2 = fma2(one2, c2, a2);
    const u64t r3 = fma2(one2, c3, a3);

    // 8) dist: dx = su*u + inv*r - si*i (packed), square, 2-SHFL reduce.
    const u64t su2  = pack2(su, su);
    const u64t nsi2 = pack2(-si, -si);
    const u64t inv2 = pack2(inv, inv);
    const u64t dx0 = fma2(su2, u0.x, fma2(nsi2, i0.x, mul2(inv2, r0)));
    const u64t dx1 = fma2(su2, u0.y, fma2(nsi2, i0.y, mul2(inv2, r1)));
    const u64t dx2 = fma2(su2, u1.x, fma2(nsi2, i1.x, mul2(inv2, r2)));
    const u64t dx3 = fma2(su2, u1.y, fma2(nsi2, i1.y, mul2(inv2, r3)));
    float d = hadd2(fma2(dx3, dx3, fma2(dx2, dx2,
                    fma2(dx1, dx1, mul2(dx0, dx0)))));
    d += __shfl_xor_sync(0xFFFFFFFFu, d, 1);
    d += __shfl_xor_sync(0xFFFFFFFFu, d, 2);

    if (sub == 0 && b < B) out[b] = -d;
}

extern "C" void kernel_launch(void* const* d_in, const int* in_sizes, int n_in,
                              void* d_out, int out_size) {
    const int*   user_ids = (const int*)  d_in[0];
    const int*   item_ids = (const int*)  d_in[1];
    const float* user_emb = (const float*)d_in[2];
    const float* item_emb = (const float*)d_in[3];
    const float* W_att    = (const float*)d_in[4];
    const float* memory   = (const float*)d_in[5];
    float* out = (float*)d_out;

    const int B = in_sizes[0];
    const int elems_per_block = (TPB / 32) * 8;  // 32
    const int grid = (B + elems_per_block - 1) / elems_per_block;
    LRML_90804198572513_kernel<<<grid, TPB>>>(
        user_ids, item_ids, user_emb, item_emb, W_att, memory, out, B);
}